// round 12
// baseline (speedup 1.0000x reference)
#include <cuda_runtime.h>
#include <math.h>

// Problem constants
#define B_  512
#define S_  100
#define D_  2
#define H_  256
#define G4_ 1024   // 4*H
#define AB  4      // batches per attention block

// ---------------- device scratch (no allocs allowed) ----------------
__device__ __align__(16) float g_hA[B_*H_];
__device__ __align__(16) float g_hB[B_*H_];
__device__ __align__(16) float g_c [B_*H_];
__device__ __align__(16) float g_encout [B_*S_*H_];   // [(b*100+s)*256 + h]
__device__ __align__(16) float g_encproj[B_*S_*H_];   // [(b*100+s)*256 + h]
__device__ __align__(16) float g_Wp_enc[H_*G4_];      // Wp[k*1024 + j*4+g] = Whh[(g*256+j)*256 + k]
__device__ __align__(16) float g_Wp_dec[H_*G4_];
__device__ __align__(16) float2 g_Wxp_enc[G4_];       // per gate-col (Wih col0, col1)
__device__ __align__(16) float2 g_Wxp_dec[G4_];
__device__ __align__(16) float2 g_bp_enc[G4_];        // (bih, bhh) gate-interleaved
__device__ __align__(16) float2 g_bp_dec[G4_];
__device__ __align__(16) float g_WeT[H_*H_];          // B[k][n] = We[n][k]
__device__ __align__(16) float g_WdT[H_*H_];          // B[k][n] = Wd[n][k]
__device__ __align__(16) float g_din[B_*D_];
__device__ __align__(16) float g_lp [B_];
__device__ unsigned char g_mask[B_*S_];

typedef unsigned long long u64;

// ---------------- packed f32x2 helpers (per-lane IEEE rn fma == scalar FFMA) ----------------
__device__ __forceinline__ u64 pk2(float lo, float hi){
    u64 r; asm("mov.b64 %0, {%1, %2};" : "=l"(r) : "f"(lo), "f"(hi)); return r;
}
__device__ __forceinline__ void fma2(u64 &d, u64 a, u64 b){
    asm("fma.rn.f32x2 %0, %1, %2, %0;" : "+l"(d) : "l"(a), "l"(b));
}
__device__ __forceinline__ float2 upk2(u64 v){
    float lo, hi; asm("mov.b64 {%0, %1}, %2;" : "=f"(lo), "=f"(hi) : "l"(v));
    return make_float2(lo, hi);
}

// ---------------- XLA:GPU-matching transcendentals (model v2) ----------------
// tanh: elemental EmitTanh rational poly, clamp +-7.90531110763549805,
// passthrough |x| < 0.0004, Horner compiled WITH fp-contraction (FMA).
__device__ __forceinline__ float tanh_x(float x){
    float xc = fminf(fmaxf(x, -7.90531110763549805f), 7.90531110763549805f);
    float x2 = __fmul_rn(xc, xc);
    float p = -2.76076847742355e-16f;
    p = __fmaf_rn(p, x2,  2.00018790482477e-13f);
    p = __fmaf_rn(p, x2, -8.60467152213735e-11f);
    p = __fmaf_rn(p, x2,  5.12229709037114e-08f);
    p = __fmaf_rn(p, x2,  1.48572235717979e-05f);
    p = __fmaf_rn(p, x2,  6.37261928875436e-04f);
    p = __fmaf_rn(p, x2,  4.89352455891786e-03f);
    p = __fmul_rn(xc, p);
    float q =  1.19825839466702e-06f;
    q = __fmaf_rn(q, x2,  1.18534705686654e-04f);
    q = __fmaf_rn(q, x2,  2.26843463243900e-03f);
    q = __fmaf_rn(q, x2,  4.89352518554385e-03f);
    float r = __fdiv_rn(p, q);
    return (fabsf(x) < 0.0004f) ? x : r;
}
// logistic: modern XLA logistic_expander EXP form: 1 / (1 + exp(-x)),
// exp = libdevice expf, IEEE division.
__device__ __forceinline__ float sigm_x(float x){
    return __fdiv_rn(1.0f, __fadd_rn(1.0f, expf(-x)));
}

// ---------------- prep: weight permutes / transposes / state init ----------------
__global__ void prep_kernel(const float* __restrict__ eWih, const float* __restrict__ eWhh,
                            const float* __restrict__ ebih, const float* __restrict__ ebhh,
                            const float* __restrict__ dWih, const float* __restrict__ dWhh,
                            const float* __restrict__ dbih, const float* __restrict__ dbhh,
                            const float* __restrict__ We,   const float* __restrict__ Wd,
                            const float* __restrict__ start)
{
    int idx0 = blockIdx.x*blockDim.x + threadIdx.x;
    int T = gridDim.x*blockDim.x;
    for (int i = idx0; i < H_*G4_; i += T){
        int k = i >> 10, n = i & 1023, j = n >> 2, g = n & 3;
        int row = g*H_ + j;
        g_Wp_enc[i] = eWhh[row*H_ + k];
        g_Wp_dec[i] = dWhh[row*H_ + k];
    }
    for (int i = idx0; i < G4_; i += T){
        int j = i >> 2, g = i & 3, row = g*H_ + j;
        g_Wxp_enc[i] = make_float2(eWih[row*2], eWih[row*2+1]);
        g_Wxp_dec[i] = make_float2(dWih[row*2], dWih[row*2+1]);
        g_bp_enc[i]  = make_float2(ebih[row], ebhh[row]);
        g_bp_dec[i]  = make_float2(dbih[row], dbhh[row]);
    }
    for (int i = idx0; i < H_*H_; i += T){
        int k = i >> 8, n = i & 255;
        g_WeT[i] = We[n*H_ + k];
        g_WdT[i] = Wd[n*H_ + k];
    }
    for (int i = idx0; i < B_*H_; i += T){ g_hA[i] = 0.f; g_c[i] = 0.f; }
    for (int i = idx0; i < B_*D_; i += T) g_din[i] = start[i & 1];
    for (int i = idx0; i < B_*S_; i += T) g_mask[i] = 0;
    for (int i = idx0; i < B_;    i += T) g_lp[i] = 0.f;
}

// ---------------- fused LSTM step: C[512,1024] = h@WhhT, gate epilogue ----------------
// grid(8,16), block(16,16). K accumulation = single sequential ascending fma chain
// per output element (bit-matches cublas fp32 sgemm / Eigen gebp).
__global__ void lstm_step_kernel(int hinpar, int dec, const float* __restrict__ xb,
                                 int xstride, int t)
{
    const float*  hin  = hinpar ? g_hB : g_hA;
    float*        hout = hinpar ? g_hA : g_hB;
    const float*  Wp   = dec ? g_Wp_dec  : g_Wp_enc;
    const float2* Wxp  = dec ? g_Wxp_dec : g_Wxp_enc;
    const float2* bp   = dec ? g_bp_dec  : g_bp_enc;
    const float*  xs   = dec ? g_din : xb;

    __shared__ float      As[64][17];
    __shared__ ulonglong2 Bs[16][16];

    int tx = threadIdx.x, ty = threadIdx.y;
    int tid = ty*16 + tx;
    int b0 = blockIdx.x*64;
    int n0 = blockIdx.y*64;

    u64 acc01[4] = {0ull,0ull,0ull,0ull};
    u64 acc23[4] = {0ull,0ull,0ull,0ull};

    for (int kc = 0; kc < 256; kc += 16){
        {   // A tile: 64x16
            int idx = tid*4;
            int r = idx >> 4, kk = idx & 15;
            float4 av = *(const float4*)(hin + (b0+r)*256 + kc + kk);
            As[r][kk]   = av.x; As[r][kk+1] = av.y;
            As[r][kk+2] = av.z; As[r][kk+3] = av.w;
        }
        {   // B tile: 16x64 packed as f32x2 pairs
            int idx = tid*4;
            int kk = idx >> 6, n = idx & 63;
            Bs[kk][n>>2] = *(const ulonglong2*)(Wp + (kc+kk)*1024 + n0 + n);
        }
        __syncthreads();
        #pragma unroll
        for (int kk = 0; kk < 16; kk++){
            ulonglong2 bb = Bs[kk][tx];
            float a0 = As[ty*4+0][kk], a1 = As[ty*4+1][kk];
            float a2 = As[ty*4+2][kk], a3 = As[ty*4+3][kk];
            u64 aa;
            aa = pk2(a0,a0); fma2(acc01[0], aa, bb.x); fma2(acc23[0], aa, bb.y);
            aa = pk2(a1,a1); fma2(acc01[1], aa, bb.x); fma2(acc23[1], aa, bb.y);
            aa = pk2(a2,a2); fma2(acc01[2], aa, bb.x); fma2(acc23[2], aa, bb.y);
            aa = pk2(a3,a3); fma2(acc01[3], aa, bb.x); fma2(acc23[3], aa, bb.y);
        }
        __syncthreads();
    }

    // epilogue. Reference order: ((x@WihT + bih) + h@WhhT) + bhh, separate rn ops.
    // x@WihT (K=2): fma(x1, w1, rn(x0*w0)) — gemm chain from 0.
    int n4 = n0 + tx*4;
    int hu = n4 >> 2;
    float2 w0 = Wxp[n4], w1 = Wxp[n4+1], w2 = Wxp[n4+2], w3 = Wxp[n4+3];
    float2 bI = bp[n4], bF = bp[n4+1], bG = bp[n4+2], bO = bp[n4+3];

    #pragma unroll
    for (int i = 0; i < 4; i++){
        int b = b0 + ty*4 + i;
        float x0 = xs[b*xstride + 0], x1 = xs[b*xstride + 1];
        float2 g01 = upk2(acc01[i]);
        float2 g23 = upk2(acc23[i]);
        float xi = __fmaf_rn(x1, w0.y, __fmul_rn(x0, w0.x));
        float xf = __fmaf_rn(x1, w1.y, __fmul_rn(x0, w1.x));
        float xg = __fmaf_rn(x1, w2.y, __fmul_rn(x0, w2.x));
        float xo = __fmaf_rn(x1, w3.y, __fmul_rn(x0, w3.x));
        float pi = __fadd_rn(__fadd_rn(__fadd_rn(xi, bI.x), g01.x), bI.y);
        float pf = __fadd_rn(__fadd_rn(__fadd_rn(xf, bF.x), g01.y), bF.y);
        float pg = __fadd_rn(__fadd_rn(__fadd_rn(xg, bG.x), g23.x), bG.y);
        float po = __fadd_rn(__fadd_rn(__fadd_rn(xo, bO.x), g23.y), bO.y);
        float ig = sigm_x(pi), fg = sigm_x(pf), gg = tanh_x(pg), og = sigm_x(po);
        int ci = b*256 + hu;
        float cn = __fadd_rn(__fmul_rn(fg, g_c[ci]), __fmul_rn(ig, gg));
        g_c[ci] = cn;
        float hv = __fmul_rn(og, tanh_x(cn));
        hout[b*256 + hu] = hv;
        if (t >= 0) g_encout[(b*100 + t)*256 + hu] = hv;
    }
}

// ---------------- enc_proj GEMM: [51200,256] x WeT + be, straight layout ----------------
// grid(800,4), block(16,16)
__global__ void encproj_kernel(const float* __restrict__ be)
{
    __shared__ float      As[64][17];
    __shared__ ulonglong2 Bs[16][16];
    int tx = threadIdx.x, ty = threadIdx.y;
    int tid = ty*16 + tx;
    int m0 = blockIdx.x*64, n0 = blockIdx.y*64;

    u64 acc01[4] = {0ull,0ull,0ull,0ull};
    u64 acc23[4] = {0ull,0ull,0ull,0ull};

    for (int kc = 0; kc < 256; kc += 16){
        {
            int idx = tid*4;
            int r = idx >> 4, kk = idx & 15;
            float4 av = *(const float4*)(g_encout + (m0+r)*256 + kc + kk);
            As[r][kk]   = av.x; As[r][kk+1] = av.y;
            As[r][kk+2] = av.z; As[r][kk+3] = av.w;
        }
        {
            int idx = tid*4;
            int kk = idx >> 6, n = idx & 63;
            Bs[kk][n>>2] = *(const ulonglong2*)(g_WeT + (kc+kk)*256 + n0 + n);
        }
        __syncthreads();
        #pragma unroll
        for (int kk = 0; kk < 16; kk++){
            ulonglong2 bb = Bs[kk][tx];
            float a0 = As[ty*4+0][kk], a1 = As[ty*4+1][kk];
            float a2 = As[ty*4+2][kk], a3 = As[ty*4+3][kk];
            u64 aa;
            aa = pk2(a0,a0); fma2(acc01[0], aa, bb.x); fma2(acc23[0], aa, bb.y);
            aa = pk2(a1,a1); fma2(acc01[1], aa, bb.x); fma2(acc23[1], aa, bb.y);
            aa = pk2(a2,a2); fma2(acc01[2], aa, bb.x); fma2(acc23[2], aa, bb.y);
            aa = pk2(a3,a3); fma2(acc01[3], aa, bb.x); fma2(acc23[3], aa, bb.y);
        }
        __syncthreads();
    }

    int nb = n0 + tx*4;
    float4 bias = *(const float4*)(be + nb);
    #pragma unroll
    for (int i = 0; i < 4; i++){
        int m = m0 + ty*4 + i;
        float2 g01 = upk2(acc01[i]);
        float2 g23 = upk2(acc23[i]);
        *(float4*)(g_encproj + m*256 + nb) =
            make_float4(__fadd_rn(g01.x, bias.x), __fadd_rn(g01.y, bias.y),
                        __fadd_rn(g23.x, bias.z), __fadd_rn(g23.y, bias.w));
    }
}

// ---------------- fused dec_proj + attention (XLA:GPU row-reduce shape) ----------------
// grid(128), block(256). Each block owns AB=4 batch items.
__global__ void attention_kernel(int t, int hpar,
                                 const float* __restrict__ x,
                                 const float* __restrict__ Vw, const float* __restrict__ Vb,
                                 const float* __restrict__ bd,
                                 float* __restrict__ tourout)
{
    const float* hin = hpar ? g_hA : g_hB;   // = hout of this step's dec LSTM
    int tid = threadIdx.x;
    int warp = tid >> 5, lane = tid & 31;
    int b0 = blockIdx.x * AB;

    __shared__ float hs [AB][256];
    __shared__ float dps[AB][256];
    __shared__ float vws[256];
    __shared__ float scs[AB][104];

    #pragma unroll
    for (int bb = 0; bb < AB; bb++)
        hs[bb][tid] = hin[(b0+bb)*256 + tid];
    vws[tid] = Vw[tid];
    __syncthreads();

    // dec_proj: n = tid, sequential ascending k (sgemm chain), + bd
    {
        float acc[AB] = {0.f,0.f,0.f,0.f};
        for (int k = 0; k < 256; k++){
            float w = g_WdT[k*256 + tid];
            #pragma unroll
            for (int bb = 0; bb < AB; bb++)
                acc[bb] = __fmaf_rn(hs[bb][k], w, acc[bb]);
        }
        float bdn = bd[tid];
        #pragma unroll
        for (int bb = 0; bb < AB; bb++)
            dps[bb][tid] = __fadd_rn(acc[bb], bdn);
    }
    __syncthreads();

    // scores: one warp per (bb,s) row, XLA row-reduce shape over h=256
    float vb0 = Vb[0];
    for (int p = warp; p < AB*100; p += 8){
        int bb = p / 100, s = p - bb*100;
        int b = b0 + bb;
        if (g_mask[b*100 + s]){
            if (lane == 0) scs[bb][s] = -INFINITY;
        } else {
            const float* ep = g_encproj + (b*100 + s)*256;
            const float* dpr = dps[bb];
            float acc = 0.f;
            #pragma unroll
            for (int j = 0; j < 8; j++){
                int h = lane + 32*j;
                float u = tanh_x(__fadd_rn(ep[h], dpr[h]));
                acc = __fmaf_rn(u, vws[h], acc);
            }
            acc = __fadd_rn(acc, __shfl_down_sync(0xffffffffu, acc, 16));
            acc = __fadd_rn(acc, __shfl_down_sync(0xffffffffu, acc, 8));
            acc = __fadd_rn(acc, __shfl_down_sync(0xffffffffu, acc, 4));
            acc = __fadd_rn(acc, __shfl_down_sync(0xffffffffu, acc, 2));
            acc = __fadd_rn(acc, __shfl_down_sync(0xffffffffu, acc, 1));
            if (lane == 0) scs[bb][s] = __fadd_rn(acc, vb0);
        }
    }
    __syncthreads();

    // per-b: max, shifted, lse, log_probs argmax (tie->min idx)
    if (warp < AB){
        int b = b0 + warp;

        // max over 100 scores (order-free, exact)
        float m = -INFINITY;
        #pragma unroll
        for (int j = 0; j < 4; j++){
            int s = lane + 32*j;
            if (s < 100) m = fmaxf(m, scs[warp][s]);
        }
        #pragma unroll
        for (int off = 16; off; off >>= 1)
            m = fmaxf(m, __shfl_xor_sync(0xffffffffu, m, off));

        // shifted = s - max (per-element rounded), lane-strided partial expf sums
        float sh[4];
        float ps = 0.f;
        #pragma unroll
        for (int j = 0; j < 4; j++){
            int s = lane + 32*j;
            sh[j] = (s < 100) ? __fsub_rn(scs[warp][s], m) : -INFINITY;
            if (s < 100) ps = __fadd_rn(ps, expf(sh[j]));
        }
        ps = __fadd_rn(ps, __shfl_down_sync(0xffffffffu, ps, 16));
        ps = __fadd_rn(ps, __shfl_down_sync(0xffffffffu, ps, 8));
        ps = __fadd_rn(ps, __shfl_down_sync(0xffffffffu, ps, 4));
        ps = __fadd_rn(ps, __shfl_down_sync(0xffffffffu, ps, 2));
        ps = __fadd_rn(ps, __shfl_down_sync(0xffffffffu, ps, 1));
        float L = logf(__shfl_sync(0xffffffffu, ps, 0));

        // log_probs = shifted - L (rounded); argmax with first-index tie-break
        float bv = -INFINITY; int bi = 1 << 30;
        #pragma unroll
        for (int j = 0; j < 4; j++){
            int s = lane + 32*j;
            if (s < 100){
                float lp = __fsub_rn(sh[j], L);
                if (lp > bv || (lp == bv && s < bi)){ bv = lp; bi = s; }
            }
        }
        #pragma unroll
        for (int off = 16; off; off >>= 1){
            float ov = __shfl_xor_sync(0xffffffffu, bv, off);
            int   oi = __shfl_xor_sync(0xffffffffu, bi, off);
            if (ov > bv || (ov == bv && oi < bi)){ bv = ov; bi = oi; }
        }

        if (lane == 0){
            g_lp[b] = __fadd_rn(g_lp[b], bv);       // lp_t[sel], ascending t
            tourout[b*100 + t] = (float)bi;
            g_mask[b*100 + bi] = 1;
            g_din[b*2 + 0] = x[b*200 + bi*2 + 0];
            g_din[b*2 + 1] = x[b*200 + bi*2 + 1];
        }
    }
}

// ---------------- write lp + final h to output ----------------
__global__ void finalize_kernel(float* __restrict__ out)
{
    int i = blockIdx.x*blockDim.x + threadIdx.x;
    if (i < 512)    out[51200 + i] = g_lp[i];
    if (i < 131072) out[51712 + i] = g_hA[i];   // decoder t=99 wrote g_hA
}

// ---------------- launch ----------------
extern "C" void kernel_launch(void* const* d_in, const int* in_sizes, int n_in,
                              void* d_out, int out_size)
{
    const float* x     = (const float*)d_in[0];
    const float* eWih  = (const float*)d_in[1];
    const float* eWhh  = (const float*)d_in[2];
    const float* ebih  = (const float*)d_in[3];
    const float* ebhh  = (const float*)d_in[4];
    const float* dWih  = (const float*)d_in[5];
    const float* dWhh  = (const float*)d_in[6];
    const float* dbih  = (const float*)d_in[7];
    const float* dbhh  = (const float*)d_in[8];
    const float* We    = (const float*)d_in[9];
    const float* be    = (const float*)d_in[10];
    const float* Wd    = (const float*)d_in[11];
    const float* bd    = (const float*)d_in[12];
    const float* Vw    = (const float*)d_in[13];
    const float* Vb    = (const float*)d_in[14];
    const float* start = (const float*)d_in[15];
    float* out = (float*)d_out;

    prep_kernel<<<1024, 256>>>(eWih,eWhh,ebih,ebhh,dWih,dWhh,dbih,dbhh,We,Wd,start);

    dim3 gl(8,16), bl(16,16);
    // encoder: h starts in g_hA (zeros); ping-pong each step
    for (int t = 0; t < 100; t++)
        lstm_step_kernel<<<gl, bl>>>(t & 1, 0, x + t*2, 200, t);

    encproj_kernel<<<dim3(800,4), bl>>>(be);

    // decoder: h in g_hA after encoder (parity 0)
    for (int t = 0; t < 100; t++){
        lstm_step_kernel<<<gl, bl>>>(t & 1, 1, nullptr, 2, -1);
        attention_kernel<<<128, 256>>>(t, t & 1, x, Vw, Vb, bd, out);
    }

    finalize_kernel<<<512, 256>>>(out);
}

// round 14
// speedup vs baseline: 1.1730x; 1.1730x over previous
#include <cuda_runtime.h>
#include <math.h>

// Problem constants
#define B_  512
#define S_  100
#define D_  2
#define H_  256
#define G4_ 1024   // 4*H

// ---------------- device scratch (no allocs allowed) ----------------
__device__ __align__(16) float g_hA[B_*H_];
__device__ __align__(16) float g_hB[B_*H_];
__device__ __align__(16) float g_c [B_*H_];
__device__ __align__(16) float g_encout [B_*S_*H_];   // [(b*100+s)*256 + h]
__device__ __align__(16) float g_encproj[B_*S_*H_];   // [(b*100+s)*256 + h]
__device__ __align__(16) float g_Wp_enc[H_*G4_];      // Wp[k*1024 + j*4+g] = Whh[(g*256+j)*256 + k]
__device__ __align__(16) float g_Wp_dec[H_*G4_];
__device__ __align__(16) float2 g_Wxp_enc[G4_];       // per gate-col (Wih col0, col1)
__device__ __align__(16) float2 g_Wxp_dec[G4_];
__device__ __align__(16) float2 g_bp_enc[G4_];        // (bih, bhh) gate-interleaved
__device__ __align__(16) float2 g_bp_dec[G4_];
__device__ __align__(16) float g_WeT[H_*H_];          // B[k][n] = We[n][k]
__device__ __align__(16) float g_WdT[H_*H_];          // B[k][n] = Wd[n][k]
__device__ __align__(16) float g_dp [B_*H_];
__device__ __align__(16) float g_din[B_*D_];
__device__ __align__(16) float g_lp [B_];
__device__ unsigned char g_mask[B_*S_];

typedef unsigned long long u64;

// ---------------- packed f32x2 helpers (per-lane IEEE rn fma == scalar FFMA) ----------------
__device__ __forceinline__ u64 pk2(float lo, float hi){
    u64 r; asm("mov.b64 %0, {%1, %2};" : "=l"(r) : "f"(lo), "f"(hi)); return r;
}
__device__ __forceinline__ void fma2(u64 &d, u64 a, u64 b){
    asm("fma.rn.f32x2 %0, %1, %2, %0;" : "+l"(d) : "l"(a), "l"(b));
}
__device__ __forceinline__ float2 upk2(u64 v){
    float lo, hi; asm("mov.b64 {%0, %1}, %2;" : "=f"(lo), "=f"(hi) : "l"(v));
    return make_float2(lo, hi);
}

// ---------------- FROZEN R12 transcendentals (bit-identical) ----------------
__device__ __forceinline__ float tanh_x(float x){
    float xc = fminf(fmaxf(x, -7.90531110763549805f), 7.90531110763549805f);
    float x2 = __fmul_rn(xc, xc);
    float p = -2.76076847742355e-16f;
    p = __fmaf_rn(p, x2,  2.00018790482477e-13f);
    p = __fmaf_rn(p, x2, -8.60467152213735e-11f);
    p = __fmaf_rn(p, x2,  5.12229709037114e-08f);
    p = __fmaf_rn(p, x2,  1.48572235717979e-05f);
    p = __fmaf_rn(p, x2,  6.37261928875436e-04f);
    p = __fmaf_rn(p, x2,  4.89352455891786e-03f);
    p = __fmul_rn(xc, p);
    float q =  1.19825839466702e-06f;
    q = __fmaf_rn(q, x2,  1.18534705686654e-04f);
    q = __fmaf_rn(q, x2,  2.26843463243900e-03f);
    q = __fmaf_rn(q, x2,  4.89352518554385e-03f);
    float r = __fdiv_rn(p, q);
    return (fabsf(x) < 0.0004f) ? x : r;
}
__device__ __forceinline__ float sigm_x(float x){
    return __fdiv_rn(1.0f, __fadd_rn(1.0f, expf(-x)));
}

// ---------------- prep: weight permutes / transposes / state init ----------------
__global__ void prep_kernel(const float* __restrict__ eWih, const float* __restrict__ eWhh,
                            const float* __restrict__ ebih, const float* __restrict__ ebhh,
                            const float* __restrict__ dWih, const float* __restrict__ dWhh,
                            const float* __restrict__ dbih, const float* __restrict__ dbhh,
                            const float* __restrict__ We,   const float* __restrict__ Wd,
                            const float* __restrict__ start)
{
    int idx0 = blockIdx.x*blockDim.x + threadIdx.x;
    int T = gridDim.x*blockDim.x;
    for (int i = idx0; i < H_*G4_; i += T){
        int k = i >> 10, n = i & 1023, j = n >> 2, g = n & 3;
        int row = g*H_ + j;
        g_Wp_enc[i] = eWhh[row*H_ + k];
        g_Wp_dec[i] = dWhh[row*H_ + k];
    }
    for (int i = idx0; i < G4_; i += T){
        int j = i >> 2, g = i & 3, row = g*H_ + j;
        g_Wxp_enc[i] = make_float2(eWih[row*2], eWih[row*2+1]);
        g_Wxp_dec[i] = make_float2(dWih[row*2], dWih[row*2+1]);
        g_bp_enc[i]  = make_float2(ebih[row], ebhh[row]);
        g_bp_dec[i]  = make_float2(dbih[row], dbhh[row]);
    }
    for (int i = idx0; i < H_*H_; i += T){
        int k = i >> 8, n = i & 255;
        g_WeT[i] = We[n*H_ + k];
        g_WdT[i] = Wd[n*H_ + k];
    }
    for (int i = idx0; i < B_*H_; i += T){ g_hA[i] = 0.f; g_c[i] = 0.f; }
    for (int i = idx0; i < B_*D_; i += T) g_din[i] = start[i & 1];
    for (int i = idx0; i < B_*S_; i += T) g_mask[i] = 0;
    for (int i = idx0; i < B_;    i += T) g_lp[i] = 0.f;
}

// ---------------- fused LSTM step v2: 32x32 tiles, double-buffered ----------------
// grid(16,32), block(8,32)=256. Thread (tx,ty): row b0+ty, cols n0+tx*4 (one hu).
// Per-output accumulation: single fma2 chain, kk ascending 0..255 — BIT-IDENTICAL to R12.
__global__ void lstm_step_kernel(int hinpar, int dec, const float* __restrict__ xb,
                                 int xstride, int t)
{
    const float*  hin  = hinpar ? g_hB : g_hA;
    float*        hout = hinpar ? g_hA : g_hB;
    const float*  Wp   = dec ? g_Wp_dec  : g_Wp_enc;
    const float2* Wxp  = dec ? g_Wxp_dec : g_Wxp_enc;
    const float2* bp   = dec ? g_bp_dec  : g_bp_enc;
    const float*  xs   = dec ? g_din : xb;

    __shared__ float      As[2][32][33];
    __shared__ ulonglong2 Bs[2][32][8];

    int tx = threadIdx.x;          // 0..7  (col group)
    int ty = threadIdx.y;          // 0..31 (row)
    int tid = ty*8 + tx;
    int b0 = blockIdx.x*32;
    int n0 = blockIdx.y*32;

    // loader indices
    int ar = tid >> 3;             // 0..31 (A row)
    int ak = (tid & 7) * 4;        // 0,4,..,28 (A k offset)
    int bk = tid >> 3;             // 0..31 (B k row)
    int bn = tid & 7;              // 0..7  (B col group)

    u64 acc01 = 0ull, acc23 = 0ull;

    // prologue: chunk 0
    float4     av = *(const float4*)(hin + (b0+ar)*256 + ak);
    ulonglong2 bv = *(const ulonglong2*)(Wp + bk*1024 + n0 + bn*4);
    As[0][ar][ak+0] = av.x; As[0][ar][ak+1] = av.y;
    As[0][ar][ak+2] = av.z; As[0][ar][ak+3] = av.w;
    Bs[0][bk][bn] = bv;
    __syncthreads();

    int buf = 0;
    #pragma unroll
    for (int c = 0; c < 8; c++){
        if (c < 7){   // prefetch next chunk into registers (overlaps compute)
            av = *(const float4*)(hin + (b0+ar)*256 + (c+1)*32 + ak);
            bv = *(const ulonglong2*)(Wp + ((c+1)*32 + bk)*1024 + n0 + bn*4);
        }
        #pragma unroll
        for (int kk = 0; kk < 32; kk++){
            float a = As[buf][ty][kk];
            ulonglong2 bb = Bs[buf][kk][tx];
            u64 aa = pk2(a, a);
            fma2(acc01, aa, bb.x);
            fma2(acc23, aa, bb.y);
        }
        if (c < 7){
            As[buf^1][ar][ak+0] = av.x; As[buf^1][ar][ak+1] = av.y;
            As[buf^1][ar][ak+2] = av.z; As[buf^1][ar][ak+3] = av.w;
            Bs[buf^1][bk][bn] = bv;
        }
        __syncthreads();
        buf ^= 1;
    }

    // epilogue (identical arithmetic to R12)
    int n4 = n0 + tx*4;
    int hu = n4 >> 2;
    float2 w0 = Wxp[n4], w1 = Wxp[n4+1], w2 = Wxp[n4+2], w3 = Wxp[n4+3];
    float2 bI = bp[n4], bF = bp[n4+1], bG = bp[n4+2], bO = bp[n4+3];

    int b = b0 + ty;
    float x0 = xs[b*xstride + 0], x1 = xs[b*xstride + 1];
    float2 g01 = upk2(acc01);
    float2 g23 = upk2(acc23);
    float xi = __fmaf_rn(x1, w0.y, __fmul_rn(x0, w0.x));
    float xf = __fmaf_rn(x1, w1.y, __fmul_rn(x0, w1.x));
    float xg = __fmaf_rn(x1, w2.y, __fmul_rn(x0, w2.x));
    float xo = __fmaf_rn(x1, w3.y, __fmul_rn(x0, w3.x));
    float pi = __fadd_rn(__fadd_rn(__fadd_rn(xi, bI.x), g01.x), bI.y);
    float pf = __fadd_rn(__fadd_rn(__fadd_rn(xf, bF.x), g01.y), bF.y);
    float pg = __fadd_rn(__fadd_rn(__fadd_rn(xg, bG.x), g23.x), bG.y);
    float po = __fadd_rn(__fadd_rn(__fadd_rn(xo, bO.x), g23.y), bO.y);
    float ig = sigm_x(pi), fg = sigm_x(pf), gg = tanh_x(pg), og = sigm_x(po);
    int ci = b*256 + hu;
    float cn = __fadd_rn(__fmul_rn(fg, g_c[ci]), __fmul_rn(ig, gg));
    g_c[ci] = cn;
    float hv = __fmul_rn(og, tanh_x(cn));
    hout[b*256 + hu] = hv;
    if (t >= 0) g_encout[(b*100 + t)*256 + hu] = hv;
}

// ---------------- enc_proj GEMM v2: 32x32 tiles, double-buffered ----------------
// grid(1600,8), block(8,32)
__global__ void encproj_kernel(const float* __restrict__ be)
{
    __shared__ float      As[2][32][33];
    __shared__ ulonglong2 Bs[2][32][8];

    int tx = threadIdx.x, ty = threadIdx.y;
    int tid = ty*8 + tx;
    int m0 = blockIdx.x*32, n0 = blockIdx.y*32;

    int ar = tid >> 3, ak = (tid & 7) * 4;
    int bk = tid >> 3, bn = tid & 7;

    u64 acc01 = 0ull, acc23 = 0ull;

    float4     av = *(const float4*)(g_encout + (m0+ar)*256 + ak);
    ulonglong2 bv = *(const ulonglong2*)(g_WeT + bk*256 + n0 + bn*4);
    As[0][ar][ak+0] = av.x; As[0][ar][ak+1] = av.y;
    As[0][ar][ak+2] = av.z; As[0][ar][ak+3] = av.w;
    Bs[0][bk][bn] = bv;
    __syncthreads();

    int buf = 0;
    #pragma unroll
    for (int c = 0; c < 8; c++){
        if (c < 7){
            av = *(const float4*)(g_encout + (m0+ar)*256 + (c+1)*32 + ak);
            bv = *(const ulonglong2*)(g_WeT + ((c+1)*32 + bk)*256 + n0 + bn*4);
        }
        #pragma unroll
        for (int kk = 0; kk < 32; kk++){
            float a = As[buf][ty][kk];
            ulonglong2 bb = Bs[buf][kk][tx];
            u64 aa = pk2(a, a);
            fma2(acc01, aa, bb.x);
            fma2(acc23, aa, bb.y);
        }
        if (c < 7){
            As[buf^1][ar][ak+0] = av.x; As[buf^1][ar][ak+1] = av.y;
            As[buf^1][ar][ak+2] = av.z; As[buf^1][ar][ak+3] = av.w;
            Bs[buf^1][bk][bn] = bv;
        }
        __syncthreads();
        buf ^= 1;
    }

    int m = m0 + ty;
    int nb = n0 + tx*4;
    float2 g01 = upk2(acc01), g23 = upk2(acc23);
    g_encproj[m*256 + nb + 0] = __fadd_rn(g01.x, be[nb+0]);
    g_encproj[m*256 + nb + 1] = __fadd_rn(g01.y, be[nb+1]);
    g_encproj[m*256 + nb + 2] = __fadd_rn(g23.x, be[nb+2]);
    g_encproj[m*256 + nb + 3] = __fadd_rn(g23.y, be[nb+3]);
}

// ---------------- dec_proj GEMM v2: [512,256] x WdT + bd ----------------
// grid(16,8), block(8,32). Same ascending-k single-chain accumulation
// (per-lane fma2 == scalar __fmaf_rn chain of R12 — bit-identical dp values).
__global__ void dp_kernel(int hpar, const float* __restrict__ bd)
{
    const float* hin = hpar ? g_hA : g_hB;

    __shared__ float      As[2][32][33];
    __shared__ ulonglong2 Bs[2][32][8];

    int tx = threadIdx.x, ty = threadIdx.y;
    int tid = ty*8 + tx;
    int b0 = blockIdx.x*32, n0 = blockIdx.y*32;

    int ar = tid >> 3, ak = (tid & 7) * 4;
    int bk = tid >> 3, bn = tid & 7;

    u64 acc01 = 0ull, acc23 = 0ull;

    float4     av = *(const float4*)(hin + (b0+ar)*256 + ak);
    ulonglong2 bv = *(const ulonglong2*)(g_WdT + bk*256 + n0 + bn*4);
    As[0][ar][ak+0] = av.x; As[0][ar][ak+1] = av.y;
    As[0][ar][ak+2] = av.z; As[0][ar][ak+3] = av.w;
    Bs[0][bk][bn] = bv;
    __syncthreads();

    int buf = 0;
    #pragma unroll
    for (int c = 0; c < 8; c++){
        if (c < 7){
            av = *(const float4*)(hin + (b0+ar)*256 + (c+1)*32 + ak);
            bv = *(const ulonglong2*)(g_WdT + ((c+1)*32 + bk)*256 + n0 + bn*4);
        }
        #pragma unroll
        for (int kk = 0; kk < 32; kk++){
            float a = As[buf][ty][kk];
            ulonglong2 bb = Bs[buf][kk][tx];
            u64 aa = pk2(a, a);
            fma2(acc01, aa, bb.x);
            fma2(acc23, aa, bb.y);
        }
        if (c < 7){
            As[buf^1][ar][ak+0] = av.x; As[buf^1][ar][ak+1] = av.y;
            As[buf^1][ar][ak+2] = av.z; As[buf^1][ar][ak+3] = av.w;
            Bs[buf^1][bk][bn] = bv;
        }
        __syncthreads();
        buf ^= 1;
    }

    int b = b0 + ty;
    int n4 = n0 + tx*4;
    float2 g01 = upk2(acc01), g23 = upk2(acc23);
    g_dp[b*256 + n4 + 0] = __fadd_rn(g01.x, bd[n4+0]);
    g_dp[b*256 + n4 + 1] = __fadd_rn(g01.y, bd[n4+1]);
    g_dp[b*256 + n4 + 2] = __fadd_rn(g23.x, bd[n4+2]);
    g_dp[b*256 + n4 + 3] = __fadd_rn(g23.y, bd[n4+3]);
}

// ---------------- attention v2: one block per batch item (grid 512) ----------------
// Scores + lse + argmax arithmetic BIT-IDENTICAL to R12 (same warp row-reduce
// shape, same rounded log_probs argmax, first-index tie-break).
__global__ void attention_kernel(int t,
                                 const float* __restrict__ x,
                                 const float* __restrict__ Vw, const float* __restrict__ Vb,
                                 float* __restrict__ tourout)
{
    int b = blockIdx.x;
    int tid = threadIdx.x;
    int warp = tid >> 5, lane = tid & 31;

    __shared__ float dps[256];
    __shared__ float vws[256];
    __shared__ float scs[104];

    dps[tid] = g_dp[b*256 + tid];
    vws[tid] = Vw[tid];
    __syncthreads();

    float vb0 = Vb[0];
    for (int s = warp; s < 100; s += 8){
        if (g_mask[b*100 + s]){
            if (lane == 0) scs[s] = -INFINITY;
        } else {
            const float* ep = g_encproj + (b*100 + s)*256;
            float acc = 0.f;
            #pragma unroll
            for (int j = 0; j < 8; j++){
                int h = lane + 32*j;
                float u = tanh_x(__fadd_rn(ep[h], dps[h]));
                acc = __fmaf_rn(u, vws[h], acc);
            }
            acc = __fadd_rn(acc, __shfl_down_sync(0xffffffffu, acc, 16));
            acc = __fadd_rn(acc, __shfl_down_sync(0xffffffffu, acc, 8));
            acc = __fadd_rn(acc, __shfl_down_sync(0xffffffffu, acc, 4));
            acc = __fadd_rn(acc, __shfl_down_sync(0xffffffffu, acc, 2));
            acc = __fadd_rn(acc, __shfl_down_sync(0xffffffffu, acc, 1));
            if (lane == 0) scs[s] = __fadd_rn(acc, vb0);
        }
    }
    __syncthreads();

    if (warp == 0){
        // max over 100 scores (order-free, exact)
        float m = -INFINITY;
        #pragma unroll
        for (int j = 0; j < 4; j++){
            int s = lane + 32*j;
            if (s < 100) m = fmaxf(m, scs[s]);
        }
        #pragma unroll
        for (int off = 16; off; off >>= 1)
            m = fmaxf(m, __shfl_xor_sync(0xffffffffu, m, off));

        // shifted + lane-strided expf partials, shfl_down tree (R12 shape)
        float sh[4];
        float ps = 0.f;
        #pragma unroll
        for (int j = 0; j < 4; j++){
            int s = lane + 32*j;
            sh[j] = (s < 100) ? __fsub_rn(scs[s], m) : -INFINITY;
            if (s < 100) ps = __fadd_rn(ps, expf(sh[j]));
        }
        ps = __fadd_rn(ps, __shfl_down_sync(0xffffffffu, ps, 16));
        ps = __fadd_rn(ps, __shfl_down_sync(0xffffffffu, ps, 8));
        ps = __fadd_rn(ps, __shfl_down_sync(0xffffffffu, ps, 4));
        ps = __fadd_rn(ps, __shfl_down_sync(0xffffffffu, ps, 2));
        ps = __fadd_rn(ps, __shfl_down_sync(0xffffffffu, ps, 1));
        float L = logf(__shfl_sync(0xffffffffu, ps, 0));

        // argmax over rounded log_probs, first-index tie-break
        float bv = -INFINITY; int bi = 1 << 30;
        #pragma unroll
        for (int j = 0; j < 4; j++){
            int s = lane + 32*j;
            if (s < 100){
                float lp = __fsub_rn(sh[j], L);
                if (lp > bv || (lp == bv && s < bi)){ bv = lp; bi = s; }
            }
        }
        #pragma unroll
        for (int off = 16; off; off >>= 1){
            float ov = __shfl_xor_sync(0xffffffffu, bv, off);
            int   oi = __shfl_xor_sync(0xffffffffu, bi, off);
            if (ov > bv || (ov == bv && oi < bi)){ bv = ov; bi = oi; }
        }

        if (lane == 0){
            g_lp[b] = __fadd_rn(g_lp[b], bv);
            tourout[b*100 + t] = (float)bi;
            g_mask[b*100 + bi] = 1;
            g_din[b*2 + 0] = x[b*200 + bi*2 + 0];
            g_din[b*2 + 1] = x[b*200 + bi*2 + 1];
        }
    }
}

// ---------------- write lp + final h to output ----------------
__global__ void finalize_kernel(float* __restrict__ out)
{
    int i = blockIdx.x*blockDim.x + threadIdx.x;
    if (i < 512)    out[51200 + i] = g_lp[i];
    if (i < 131072) out[51712 + i] = g_hA[i];   // decoder t=99 wrote g_hA
}

// ---------------- launch ----------------
extern "C" void kernel_launch(void* const* d_in, const int* in_sizes, int n_in,
                              void* d_out, int out_size)
{
    const float* x     = (const float*)d_in[0];
    const float* eWih  = (const float*)d_in[1];
    const float* eWhh  = (const float*)d_in[2];
    const float* ebih  = (const float*)d_in[3];
    const float* ebhh  = (const float*)d_in[4];
    const float* dWih  = (const float*)d_in[5];
    const float* dWhh  = (const float*)d_in[6];
    const float* dbih  = (const float*)d_in[7];
    const float* dbhh  = (const float*)d_in[8];
    const float* We    = (const float*)d_in[9];
    const float* be    = (const float*)d_in[10];
    const float* Wd    = (const float*)d_in[11];
    const float* bd    = (const float*)d_in[12];
    const float* Vw    = (const float*)d_in[13];
    const float* Vb    = (const float*)d_in[14];
    const float* start = (const float*)d_in[15];
    float* out = (float*)d_out;

    prep_kernel<<<1024, 256>>>(eWih,eWhh,ebih,ebhh,dWih,dWhh,dbih,dbhh,We,Wd,start);

    dim3 bl(8,32);
    dim3 gl(16,32);
    // encoder: h starts in g_hA (zeros); ping-pong each step
    for (int t = 0; t < 100; t++)
        lstm_step_kernel<<<gl, bl>>>(t & 1, 0, x + t*2, 200, t);

    encproj_kernel<<<dim3(1600,8), bl>>>(be);

    // decoder: h in g_hA after encoder (parity 0)
    for (int t = 0; t < 100; t++){
        lstm_step_kernel<<<gl, bl>>>(t & 1, 1, nullptr, 2, -1);
        dp_kernel<<<dim3(16,8), bl>>>(t & 1, bd);
        attention_kernel<<<512, 256>>>(t, x, Vw, Vb, out);
    }

    finalize_kernel<<<512, 256>>>(out);
}

// round 17
// speedup vs baseline: 2.2753x; 1.9397x over previous
#include <cuda_runtime.h>
#include <math.h>

// Problem constants
#define B_  512
#define S_  100
#define D_  2
#define H_  256
#define G4_ 1024   // 4*H

// ---------------- device scratch (no allocs allowed) ----------------
__device__ __align__(16) float g_hA[B_*H_];
__device__ __align__(16) float g_hB[B_*H_];
__device__ __align__(16) float g_c [B_*H_];
__device__ __align__(16) float g_encout [B_*S_*H_];   // [(b*100+s)*256 + h]
__device__ __align__(16) float g_encproj[B_*S_*H_];   // [(b*100+s)*256 + h]
__device__ __align__(16) float g_Wp_enc[H_*G4_];      // Wp[k*1024 + j*4+g] = Whh[(g*256+j)*256 + k]
__device__ __align__(16) float g_Wp_dec[H_*G4_];
__device__ __align__(16) float2 g_Wxp_enc[G4_];       // per gate-col (Wih col0, col1)
__device__ __align__(16) float2 g_Wxp_dec[G4_];
__device__ __align__(16) float2 g_bp_enc[G4_];        // (bih, bhh) gate-interleaved
__device__ __align__(16) float2 g_bp_dec[G4_];
__device__ __align__(16) float g_WeT[H_*H_];          // B[k][n] = We[n][k]
__device__ __align__(16) float g_WdT[H_*H_];          // B[k][n] = Wd[n][k]
__device__ __align__(16) float g_din[B_*D_];
__device__ __align__(16) float g_lp [B_];
__device__ unsigned char g_mask[B_*S_];

typedef unsigned long long u64;

// ---------------- packed f32x2 helpers (per-lane IEEE rn fma == scalar FFMA) ----------------
__device__ __forceinline__ u64 pk2(float lo, float hi){
    u64 r; asm("mov.b64 %0, {%1, %2};" : "=l"(r) : "f"(lo), "f"(hi)); return r;
}
__device__ __forceinline__ void fma2(u64 &d, u64 a, u64 b){
    asm("fma.rn.f32x2 %0, %1, %2, %0;" : "+l"(d) : "l"(a), "l"(b));
}
__device__ __forceinline__ float2 upk2(u64 v){
    float lo, hi; asm("mov.b64 {%0, %1}, %2;" : "=f"(lo), "=f"(hi) : "l"(v));
    return make_float2(lo, hi);
}

// ---------------- FROZEN R12 transcendentals (bit-identical) ----------------
__device__ __forceinline__ float tanh_x(float x){
    float xc = fminf(fmaxf(x, -7.90531110763549805f), 7.90531110763549805f);
    float x2 = __fmul_rn(xc, xc);
    float p = -2.76076847742355e-16f;
    p = __fmaf_rn(p, x2,  2.00018790482477e-13f);
    p = __fmaf_rn(p, x2, -8.60467152213735e-11f);
    p = __fmaf_rn(p, x2,  5.12229709037114e-08f);
    p = __fmaf_rn(p, x2,  1.48572235717979e-05f);
    p = __fmaf_rn(p, x2,  6.37261928875436e-04f);
    p = __fmaf_rn(p, x2,  4.89352455891786e-03f);
    p = __fmul_rn(xc, p);
    float q =  1.19825839466702e-06f;
    q = __fmaf_rn(q, x2,  1.18534705686654e-04f);
    q = __fmaf_rn(q, x2,  2.26843463243900e-03f);
    q = __fmaf_rn(q, x2,  4.89352518554385e-03f);
    float r = __fdiv_rn(p, q);
    return (fabsf(x) < 0.0004f) ? x : r;
}
__device__ __forceinline__ float sigm_x(float x){
    return __fdiv_rn(1.0f, __fadd_rn(1.0f, expf(-x)));
}

// ---------------- prep: weight permutes / transposes / state init ----------------
__global__ void prep_kernel(const float* __restrict__ eWih, const float* __restrict__ eWhh,
                            const float* __restrict__ ebih, const float* __restrict__ ebhh,
                            const float* __restrict__ dWih, const float* __restrict__ dWhh,
                            const float* __restrict__ dbih, const float* __restrict__ dbhh,
                            const float* __restrict__ We,   const float* __restrict__ Wd,
                            const float* __restrict__ start)
{
    int idx0 = blockIdx.x*blockDim.x + threadIdx.x;
    int T = gridDim.x*blockDim.x;
    for (int i = idx0; i < H_*G4_; i += T){
        int k = i >> 10, n = i & 1023, j = n >> 2, g = n & 3;
        int row = g*H_ + j;
        g_Wp_enc[i] = eWhh[row*H_ + k];
        g_Wp_dec[i] = dWhh[row*H_ + k];
    }
    for (int i = idx0; i < G4_; i += T){
        int j = i >> 2, g = i & 3, row = g*H_ + j;
        g_Wxp_enc[i] = make_float2(eWih[row*2], eWih[row*2+1]);
        g_Wxp_dec[i] = make_float2(dWih[row*2], dWih[row*2+1]);
        g_bp_enc[i]  = make_float2(ebih[row], ebhh[row]);
        g_bp_dec[i]  = make_float2(dbih[row], dbhh[row]);
    }
    for (int i = idx0; i < H_*H_; i += T){
        int k = i >> 8, n = i & 255;
        g_WeT[i] = We[n*H_ + k];
        g_WdT[i] = Wd[n*H_ + k];
    }
    for (int i = idx0; i < B_*H_; i += T){ g_hA[i] = 0.f; g_c[i] = 0.f; }
    for (int i = idx0; i < B_*D_; i += T) g_din[i] = start[i & 1];
    for (int i = idx0; i < B_*S_; i += T) g_mask[i] = 0;
    for (int i = idx0; i < B_;    i += T) g_lp[i] = 0.f;
}

// ---------------- fused LSTM step v3: 32(b)x64(n) tiles, 2x4 micro, double-buffered ----
// grid(16,16), block(16,16)=256. Thread (tx,ty): rows b0+ty*2+{0,1}, cols n0+tx*4
// (one hidden unit's 4 gates). Per-output accumulation: single fma2 chain,
// kk ascending 0..255 — BIT-IDENTICAL to R12/R14.
__global__ void lstm_step_kernel(int hinpar, int dec, const float* __restrict__ xb,
                                 int xstride, int t)
{
    const float*  hin  = hinpar ? g_hB : g_hA;
    float*        hout = hinpar ? g_hA : g_hB;
    const float*  Wp   = dec ? g_Wp_dec  : g_Wp_enc;
    const float2* Wxp  = dec ? g_Wxp_dec : g_Wxp_enc;
    const float2* bp   = dec ? g_bp_dec  : g_bp_enc;
    const float*  xs   = dec ? g_din : xb;

    __shared__ float      As[2][32][33];
    __shared__ ulonglong2 Bs[2][32][16];

    int tx = threadIdx.x;          // 0..15 (col group: 4 cols)
    int ty = threadIdx.y;          // 0..15 (row pair)
    int tid = ty*16 + tx;
    int b0 = blockIdx.x*32;
    int n0 = blockIdx.y*64;

    // loader indices: A tile 32x32 floats (4/thread), B tile 32x64 floats (8/thread)
    int ar = tid >> 3;             // 0..31
    int ak = (tid & 7) * 4;        // 0..28
    int bk = tid >> 4;             // 0..15 (and +16)
    int bn = tid & 15;             // 0..15

    u64 a00 = 0ull, a01 = 0ull;    // row 0: cols 0-1, 2-3
    u64 a10 = 0ull, a11 = 0ull;    // row 1

    // prologue: chunk 0
    float4     av  = *(const float4*)(hin + (b0+ar)*256 + ak);
    ulonglong2 bv0 = *(const ulonglong2*)(Wp + bk*1024 + n0 + bn*4);
    ulonglong2 bv1 = *(const ulonglong2*)(Wp + (bk+16)*1024 + n0 + bn*4);
    As[0][ar][ak+0] = av.x; As[0][ar][ak+1] = av.y;
    As[0][ar][ak+2] = av.z; As[0][ar][ak+3] = av.w;
    Bs[0][bk][bn] = bv0;
    Bs[0][bk+16][bn] = bv1;
    __syncthreads();

    int buf = 0;
    #pragma unroll
    for (int c = 0; c < 8; c++){
        if (c < 7){   // prefetch next chunk into registers (overlaps compute)
            av  = *(const float4*)(hin + (b0+ar)*256 + (c+1)*32 + ak);
            bv0 = *(const ulonglong2*)(Wp + ((c+1)*32 + bk)*1024 + n0 + bn*4);
            bv1 = *(const ulonglong2*)(Wp + ((c+1)*32 + bk+16)*1024 + n0 + bn*4);
        }
        #pragma unroll
        for (int kk = 0; kk < 32; kk++){
            float a0 = As[buf][ty*2+0][kk];
            float a1 = As[buf][ty*2+1][kk];
            ulonglong2 bb = Bs[buf][kk][tx];
            u64 p0 = pk2(a0, a0);
            u64 p1 = pk2(a1, a1);
            fma2(a00, p0, bb.x); fma2(a01, p0, bb.y);
            fma2(a10, p1, bb.x); fma2(a11, p1, bb.y);
        }
        if (c < 7){
            As[buf^1][ar][ak+0] = av.x; As[buf^1][ar][ak+1] = av.y;
            As[buf^1][ar][ak+2] = av.z; As[buf^1][ar][ak+3] = av.w;
            Bs[buf^1][bk][bn] = bv0;
            Bs[buf^1][bk+16][bn] = bv1;
        }
        __syncthreads();
        buf ^= 1;
    }

    // epilogue (identical arithmetic to R12/R14)
    int n4 = n0 + tx*4;
    int hu = n4 >> 2;
    float2 w0 = Wxp[n4], w1 = Wxp[n4+1], w2 = Wxp[n4+2], w3 = Wxp[n4+3];
    float2 bI = bp[n4], bF = bp[n4+1], bG = bp[n4+2], bO = bp[n4+3];

    #pragma unroll
    for (int r = 0; r < 2; r++){
        int b = b0 + ty*2 + r;
        float x0 = xs[b*xstride + 0], x1 = xs[b*xstride + 1];
        float2 g01 = upk2(r ? a10 : a00);
        float2 g23 = upk2(r ? a11 : a01);
        float xi = __fmaf_rn(x1, w0.y, __fmul_rn(x0, w0.x));
        float xf = __fmaf_rn(x1, w1.y, __fmul_rn(x0, w1.x));
        float xg = __fmaf_rn(x1, w2.y, __fmul_rn(x0, w2.x));
        float xo = __fmaf_rn(x1, w3.y, __fmul_rn(x0, w3.x));
        float pi = __fadd_rn(__fadd_rn(__fadd_rn(xi, bI.x), g01.x), bI.y);
        float pf = __fadd_rn(__fadd_rn(__fadd_rn(xf, bF.x), g01.y), bF.y);
        float pg = __fadd_rn(__fadd_rn(__fadd_rn(xg, bG.x), g23.x), bG.y);
        float po = __fadd_rn(__fadd_rn(__fadd_rn(xo, bO.x), g23.y), bO.y);
        float ig = sigm_x(pi), fg = sigm_x(pf), gg = tanh_x(pg), og = sigm_x(po);
        int ci = b*256 + hu;
        float cn = __fadd_rn(__fmul_rn(fg, g_c[ci]), __fmul_rn(ig, gg));
        g_c[ci] = cn;
        float hv = __fmul_rn(og, tanh_x(cn));
        hout[b*256 + hu] = hv;
        if (t >= 0) g_encout[(b*100 + t)*256 + hu] = hv;
    }
}

// ---------------- enc_proj GEMM: 32x32 tiles, double-buffered (R14, unchanged) ----------
// grid(1600,8), block(8,32)
__global__ void encproj_kernel(const float* __restrict__ be)
{
    __shared__ float      As[2][32][33];
    __shared__ ulonglong2 Bs[2][32][8];

    int tx = threadIdx.x, ty = threadIdx.y;
    int tid = ty*8 + tx;
    int m0 = blockIdx.x*32, n0 = blockIdx.y*32;

    int ar = tid >> 3, ak = (tid & 7) * 4;
    int bk = tid >> 3, bn = tid & 7;

    u64 acc01 = 0ull, acc23 = 0ull;

    float4     av = *(const float4*)(g_encout + (m0+ar)*256 + ak);
    ulonglong2 bv = *(const ulonglong2*)(g_WeT + bk*256 + n0 + bn*4);
    As[0][ar][ak+0] = av.x; As[0][ar][ak+1] = av.y;
    As[0][ar][ak+2] = av.z; As[0][ar][ak+3] = av.w;
    Bs[0][bk][bn] = bv;
    __syncthreads();

    int buf = 0;
    #pragma unroll
    for (int c = 0; c < 8; c++){
        if (c < 7){
            av = *(const float4*)(g_encout + (m0+ar)*256 + (c+1)*32 + ak);
            bv = *(const ulonglong2*)(g_WeT + ((c+1)*32 + bk)*256 + n0 + bn*4);
        }
        #pragma unroll
        for (int kk = 0; kk < 32; kk++){
            float a = As[buf][ty][kk];
            ulonglong2 bb = Bs[buf][kk][tx];
            u64 aa = pk2(a, a);
            fma2(acc01, aa, bb.x);
            fma2(acc23, aa, bb.y);
        }
        if (c < 7){
            As[buf^1][ar][ak+0] = av.x; As[buf^1][ar][ak+1] = av.y;
            As[buf^1][ar][ak+2] = av.z; As[buf^1][ar][ak+3] = av.w;
            Bs[buf^1][bk][bn] = bv;
        }
        __syncthreads();
        buf ^= 1;
    }

    int m = m0 + ty;
    int nb = n0 + tx*4;
    float2 g01 = upk2(acc01), g23 = upk2(acc23);
    g_encproj[m*256 + nb + 0] = __fadd_rn(g01.x, be[nb+0]);
    g_encproj[m*256 + nb + 1] = __fadd_rn(g01.y, be[nb+1]);
    g_encproj[m*256 + nb + 2] = __fadd_rn(g23.x, be[nb+2]);
    g_encproj[m*256 + nb + 3] = __fadd_rn(g23.y, be[nb+3]);
}

// ---------------- attention v3: fused dec_proj, one block per batch item ----------------
// dp: per-thread scalar ascending-k __fmaf_rn chain == per-lane fma2 chain of the
// old dp_kernel (bit-identical). Scores + lse + argmax BIT-IDENTICAL to R14.
__global__ void attention_kernel(int t, int hpar,
                                 const float* __restrict__ x,
                                 const float* __restrict__ Vw, const float* __restrict__ Vb,
                                 const float* __restrict__ bd,
                                 float* __restrict__ tourout)
{
    const float* hin = hpar ? g_hA : g_hB;   // = hout of this step's dec LSTM
    int b = blockIdx.x;
    int tid = threadIdx.x;
    int warp = tid >> 5, lane = tid & 31;

    __shared__ float hs [256];
    __shared__ float dps[256];
    __shared__ float vws[256];
    __shared__ float scs[104];

    hs[tid]  = hin[b*256 + tid];
    vws[tid] = Vw[tid];
    __syncthreads();

    // dec_proj: n = tid, sequential ascending k, + bd
    {
        float acc = 0.f;
        #pragma unroll 4
        for (int k = 0; k < 256; k++)
            acc = __fmaf_rn(hs[k], g_WdT[k*256 + tid], acc);
        dps[tid] = __fadd_rn(acc, bd[tid]);
    }
    __syncthreads();

    // scores: one warp per s row, XLA row-reduce shape over h=256
    float vb0 = Vb[0];
    for (int s = warp; s < 100; s += 8){
        if (g_mask[b*100 + s]){
            if (lane == 0) scs[s] = -INFINITY;
        } else {
            const float* ep = g_encproj + (b*100 + s)*256;
            float acc = 0.f;
            #pragma unroll
            for (int j = 0; j < 8; j++){
                int h = lane + 32*j;
                float u = tanh_x(__fadd_rn(ep[h], dps[h]));
                acc = __fmaf_rn(u, vws[h], acc);
            }
            acc = __fadd_rn(acc, __shfl_down_sync(0xffffffffu, acc, 16));
            acc = __fadd_rn(acc, __shfl_down_sync(0xffffffffu, acc, 8));
            acc = __fadd_rn(acc, __shfl_down_sync(0xffffffffu, acc, 4));
            acc = __fadd_rn(acc, __shfl_down_sync(0xffffffffu, acc, 2));
            acc = __fadd_rn(acc, __shfl_down_sync(0xffffffffu, acc, 1));
            if (lane == 0) scs[s] = __fadd_rn(acc, vb0);
        }
    }
    __syncthreads();

    if (warp == 0){
        // max over 100 scores (order-free, exact)
        float m = -INFINITY;
        #pragma unroll
        for (int j = 0; j < 4; j++){
            int s = lane + 32*j;
            if (s < 100) m = fmaxf(m, scs[s]);
        }
        #pragma unroll
        for (int off = 16; off; off >>= 1)
            m = fmaxf(m, __shfl_xor_sync(0xffffffffu, m, off));

        // shifted + lane-strided expf partials, shfl_down tree (R12 shape)
        float sh[4];
        float ps = 0.f;
        #pragma unroll
        for (int j = 0; j < 4; j++){
            int s = lane + 32*j;
            sh[j] = (s < 100) ? __fsub_rn(scs[s], m) : -INFINITY;
            if (s < 100) ps = __fadd_rn(ps, expf(sh[j]));
        }
        ps = __fadd_rn(ps, __shfl_down_sync(0xffffffffu, ps, 16));
        ps = __fadd_rn(ps, __shfl_down_sync(0xffffffffu, ps, 8));
        ps = __fadd_rn(ps, __shfl_down_sync(0xffffffffu, ps, 4));
        ps = __fadd_rn(ps, __shfl_down_sync(0xffffffffu, ps, 2));
        ps = __fadd_rn(ps, __shfl_down_sync(0xffffffffu, ps, 1));
        float L = logf(__shfl_sync(0xffffffffu, ps, 0));

        // argmax over rounded log_probs, first-index tie-break
        float bv = -INFINITY; int bi = 1 << 30;
        #pragma unroll
        for (int j = 0; j < 4; j++){
            int s = lane + 32*j;
            if (s < 100){
                float lp = __fsub_rn(sh[j], L);
                if (lp > bv || (lp == bv && s < bi)){ bv = lp; bi = s; }
            }
        }
        #pragma unroll
        for (int off = 16; off; off >>= 1){
            float ov = __shfl_xor_sync(0xffffffffu, bv, off);
            int   oi = __shfl_xor_sync(0xffffffffu, bi, off);
            if (ov > bv || (ov == bv && oi < bi)){ bv = ov; bi = oi; }
        }

        if (lane == 0){
            g_lp[b] = __fadd_rn(g_lp[b], bv);
            tourout[b*100 + t] = (float)bi;
            g_mask[b*100 + bi] = 1;
            g_din[b*2 + 0] = x[b*200 + bi*2 + 0];
            g_din[b*2 + 1] = x[b*200 + bi*2 + 1];
        }
    }
}

// ---------------- write lp + final h to output ----------------
__global__ void finalize_kernel(float* __restrict__ out)
{
    int i = blockIdx.x*blockDim.x + threadIdx.x;
    if (i < 512)    out[51200 + i] = g_lp[i];
    if (i < 131072) out[51712 + i] = g_hA[i];   // decoder t=99 wrote g_hA
}

// ---------------- launch ----------------
extern "C" void kernel_launch(void* const* d_in, const int* in_sizes, int n_in,
                              void* d_out, int out_size)
{
    const float* x     = (const float*)d_in[0];
    const float* eWih  = (const float*)d_in[1];
    const float* eWhh  = (const float*)d_in[2];
    const float* ebih  = (const float*)d_in[3];
    const float* ebhh  = (const float*)d_in[4];
    const float* dWih  = (const float*)d_in[5];
    const float* dWhh  = (const float*)d_in[6];
    const float* dbih  = (const float*)d_in[7];
    const float* dbhh  = (const float*)d_in[8];
    const float* We    = (const float*)d_in[9];
    const float* be    = (const float*)d_in[10];
    const float* Wd    = (const float*)d_in[11];
    const float* bd    = (const float*)d_in[12];
    const float* Vw    = (const float*)d_in[13];
    const float* Vb    = (const float*)d_in[14];
    const float* start = (const float*)d_in[15];
    float* out = (float*)d_out;

    prep_kernel<<<1024, 256>>>(eWih,eWhh,ebih,ebhh,dWih,dWhh,dbih,dbhh,We,Wd,start);

    dim3 bl(16,16);
    dim3 gl(16,16);
    // encoder: h starts in g_hA (zeros); ping-pong each step
    for (int t = 0; t < 100; t++)
        lstm_step_kernel<<<gl, bl>>>(t & 1, 0, x + t*2, 200, t);

    encproj_kernel<<<dim3(1600,8), dim3(8,32)>>>(be);

    // decoder: h in g_hA after encoder (parity 0)
    for (int t = 0; t < 100; t++){
        lstm_step_kernel<<<gl, bl>>>(t & 1, 1, nullptr, 2, -1);
        attention_kernel<<<512, 256>>>(t, t & 1, x, Vw, Vb, bd, out);
    }

    finalize_kernel<<<512, 256>>>(out);
}